// round 16
// baseline (speedup 1.0000x reference)
#include <cuda_runtime.h>
#include <cuda_fp16.h>
#include <cstdint>
#include <cstddef>
#include <mma.h>

using namespace nvcuda;

// ---------------------------------------------------------------------------
// Problem: N=4096, D=128, R=8, OUT=128, B=4096
// Node-dedup + persistent K-split stage1:
//   compact: distinct nodes referenced by head_idx||tail_idx -> list (~3542)
//   stage1 (persistent, dense, reg-fused cvt):
//       upd_all[node][r*128+d] += sum_{n in split} adj[r,node,n]*emb[n,d]
//       work units (tile, r, split) pulled from an atomic queue
//   stage2 (gather, BM=64): out[m][o] = sum_k A2[m][k]*B2[k][o]
//       A2[m][k<1024] = upd_all[idx_m][k],  A2[m][1024+dd] = e_m[dd]
//       B2[k<1024][o] = relK_flat[k][o],    B2[1024+dd][o] = selfK[dd][o]
// Legacy wmma fp16 only (compute_103 PTX: no tcgen05).
// ---------------------------------------------------------------------------

#define NN    4096
#define DD    128
#define RR    8
#define OUTD  128
#define KU    (RR * DD)            // 1024
#define K2    (KU + DD)            // 1152

// Device-global scratch (no allocation):
__device__ __half g_emb_h[NN * DD];                // 1 MB
__device__ __half g_upd_h[(size_t)NN * KU];        // 8 MB  [node][r*128+d]
__device__ __half g_eh[(size_t)2 * NN * DD];       // 2 MB  [m][d] (head||tail)
__device__ __half g_Bh[K2 * OUTD];                 // 288 KB [k][o]
__device__ int    g_list[NN];                      // compacted node ids
__device__ int    g_cnt;                           // number of distinct nodes
__device__ int    g_work;                          // persistent work counter

__device__ __forceinline__ void cp_async16(uint32_t dst, const void* src) {
    asm volatile("cp.async.cg.shared.global [%0], [%1], 16;\n"
                 :: "r"(dst), "l"(src));
}
__device__ __forceinline__ void cp_commit() {
    asm volatile("cp.async.commit_group;\n" ::: "memory");
}

// ---------------------------------------------------------------------------
// Kernel 0: zero output + zero g_upd_h + zero g_work + convert inputs -> fp16
// grid 2048 x 256 = 524288 threads
// ---------------------------------------------------------------------------
__global__ void prep_kernel(float4* __restrict__ out,
                            const float2* __restrict__ emb2,
                            const float2* __restrict__ head_e2,
                            const float2* __restrict__ tail_e2,
                            const float2* __restrict__ relK2,
                            const float2* __restrict__ selfK2) {
    int i = blockIdx.x * blockDim.x + threadIdx.x;     // 0..524287
    if (i == 0) g_work = 0;
    if (i < 262144) out[i] = make_float4(0.f, 0.f, 0.f, 0.f);
    // zero g_upd_h: 8 MB = 524288 x 16 B
    {
        uint4 z = make_uint4(0u, 0u, 0u, 0u);
        ((uint4*)g_upd_h)[i] = z;
    }
    if (i < NN * DD / 2) {                             // emb
        float2 v = emb2[i];
        ((__half2*)g_emb_h)[i] = __floats2half2_rn(v.x, v.y);
    }
    if (i < 2 * NN * DD / 2) {                         // e (head||tail)
        float2 v = (i < NN * DD / 2) ? head_e2[i] : tail_e2[i - NN * DD / 2];
        ((__half2*)g_eh)[i] = __floats2half2_rn(v.x, v.y);
    }
    if (i < K2 * OUTD / 2) {                           // B2 (relK||selfK)
        float2 v = (i < KU * OUTD / 2) ? relK2[i] : selfK2[i - KU * OUTD / 2];
        ((__half2*)g_Bh)[i] = __floats2half2_rn(v.x, v.y);
    }
}

// ---------------------------------------------------------------------------
// Kernel 1: compact — build distinct-node list from head_idx||tail_idx.
// Single block, 1024 threads. Shared: 2 x 4096 ints (32 KB) scan buffers.
// ---------------------------------------------------------------------------
__global__ __launch_bounds__(1024) void compact_kernel(
    const int* __restrict__ head_idx,
    const int* __restrict__ tail_idx) {
    __shared__ int sA[NN];
    __shared__ int sB[NN];
    const int tid = threadIdx.x;

#pragma unroll
    for (int k = 0; k < 4; k++) sA[tid + k * 1024] = 0;
    __syncthreads();
#pragma unroll
    for (int k = 0; k < 8; k++) {
        int q = tid + k * 1024;                 // 0..8191
        int v = (q < 4096) ? head_idx[q] : tail_idx[q - 4096];
        sA[v] = 1;
    }
    __syncthreads();
    int m[4];
#pragma unroll
    for (int k = 0; k < 4; k++) m[k] = sA[tid + k * 1024];
    int* src = sA;
    int* dst = sB;
    for (int off = 1; off < NN; off <<= 1) {
#pragma unroll
        for (int k = 0; k < 4; k++) {
            int i = tid + k * 1024;
            int v = src[i];
            if (i >= off) v += src[i - off];
            dst[i] = v;
        }
        __syncthreads();
        int* t = src; src = dst; dst = t;
    }
    int cnt = src[NN - 1];
#pragma unroll
    for (int k = 0; k < 4; k++) {
        int i = tid + k * 1024;
        int rank = src[i] - m[k];
        if (m[k]) g_list[rank] = i;
        if (i >= cnt) g_list[i] = 0;            // pad tail with a valid node
    }
    if (tid == 0) g_cnt = cnt;
}

// ---------------------------------------------------------------------------
// wmma fragment types
// ---------------------------------------------------------------------------
typedef wmma::fragment<wmma::matrix_a, 16, 16, 16, __half, wmma::row_major> HFragA;
typedef wmma::fragment<wmma::matrix_b, 16, 16, 16, __half, wmma::row_major> HFragB;
typedef wmma::fragment<wmma::accumulator, 16, 16, 16, float> HFragC;

// ---------------------------------------------------------------------------
// Kernel 2: stage1 persistent dense GEMM, register-fused A conversion.
//   grid.x = 304 (2/SM). Units: w -> tile = w % ntiles, rs = w / ntiles,
//   r = rs & 7, split = rs >> 3. Unit = 128 nodes x 128 d, K = 1024 (32xBK32).
//   Epilogue: fp16 half2 atomicAdd into g_upd_h (zeroed in prep).
// SMEM: Ah 2 x 128 x 40 halves [0,20480); B16 3 x 32 x 136 halves
// [20480,46592). Epilogue reuses smem as 128x132 fp32 (67584 B = alloc).
// ---------------------------------------------------------------------------
#define AH_LD     40
#define AH_STG_B  10240
#define B16_LD    136
#define B16_STG_B 8704
#define OFF_AH    0
#define OFF_B16   20480
#define SMEM_S1   (128 * 132 * 4)       // 67584
#define S1_NIT    32                    // 1024 / 32

__global__ __launch_bounds__(128, 2) void stage1_kernel(
    const float* __restrict__ adj)       // [8,4096,4096] fp32
{
    extern __shared__ char smc[];
    __shared__ int nl[128];
    __shared__ int swork;

    const int tid = threadIdx.x;
    const int wid = tid >> 5;
    const uint32_t sm32 = (uint32_t)__cvta_generic_to_shared(smc);

    const int cnt     = g_cnt;
    const int ntiles  = (cnt + 127) >> 7;
    const int n_units = ntiles * 32;     // 8 r x 4 splits

    const int brow = tid >> 2;           // B loader row
    const int bh0  = (tid & 3) * 32;     // B loader half offset
    const int wm   = (wid >> 1) * 64;
    const int wn   = (wid & 1) * 64;

    for (;;) {
        if (tid == 0) swork = atomicAdd(&g_work, 1);
        __syncthreads();
        const int w = swork;
        if (w >= n_units) break;         // uniform exit

        const int rs    = w / ntiles;
        const int tile  = w - rs * ntiles;
        const int r     = rs & 7;
        const int split = rs >> 3;
        const int node0 = tile * 128;
        const int nbase = split * 1024;

        nl[tid] = g_list[node0 + tid];
        __syncthreads();

        const float* adjrow = adj + ((size_t)r << 24)
                            + (size_t)nl[tid] * NN + nbase;

        auto issueB = [&](int j) {
            const int s = j % 3;
            const int n0 = nbase + j * 32;
            const uint32_t b_dst = sm32 + OFF_B16 + (uint32_t)s * B16_STG_B
                                 + (uint32_t)(brow * B16_LD + bh0) * 2;
            const __half* bsrc = g_emb_h + (size_t)(n0 + brow) * DD + bh0;
#pragma unroll
            for (int c = 0; c < 4; c++)
                cp_async16(b_dst + c * 16, bsrc + c * 8);
        };

        HFragC acc[4][4];
#pragma unroll
        for (int i = 0; i < 4; i++)
#pragma unroll
            for (int j = 0; j < 4; j++) wmma::fill_fragment(acc[i][j], 0.0f);

        // prologue: A regs for iter 0; B stages 0,1
        float4 abuf[8];
#pragma unroll
        for (int q = 0; q < 8; q++) abuf[q] = *(const float4*)(adjrow + q * 4);
        issueB(0); cp_commit();
        issueB(1); cp_commit();

        for (int it = 0; it < S1_NIT; it++) {
            const int s = it % 3;
            asm volatile("cp.async.wait_group 1;\n" ::: "memory");

            // convert abuf -> Ah[it&1], 32 halves = 4 x STS.128
            {
                __half* dst = (__half*)(smc + OFF_AH + (it & 1) * AH_STG_B)
                            + tid * AH_LD;
#pragma unroll
                for (int q = 0; q < 4; q++) {
                    float4 v0 = abuf[2 * q];
                    float4 v1 = abuf[2 * q + 1];
                    __half2 h0 = __floats2half2_rn(v0.x, v0.y);
                    __half2 h1 = __floats2half2_rn(v0.z, v0.w);
                    __half2 h2 = __floats2half2_rn(v1.x, v1.y);
                    __half2 h3 = __floats2half2_rn(v1.z, v1.w);
                    uint4 wv;
                    wv.x = *(const uint32_t*)&h0;
                    wv.y = *(const uint32_t*)&h1;
                    wv.z = *(const uint32_t*)&h2;
                    wv.w = *(const uint32_t*)&h3;
                    *(uint4*)(dst + q * 8) = wv;
                }
            }
            if (it + 1 < S1_NIT) {
                const float* src = adjrow + (it + 1) * 32;
#pragma unroll
                for (int q = 0; q < 8; q++)
                    abuf[q] = *(const float4*)(src + q * 4);
            }

            __syncthreads();   // publish Ah[it&1] + B stage s; close wmma_{it-1}

            if (it + 2 < S1_NIT) issueB(it + 2);
            cp_commit();

            const __half* Aw = (const __half*)(smc + OFF_AH + (it & 1) * AH_STG_B)
                             + wm * AH_LD;
            const __half* Bw = (const __half*)(smc + OFF_B16 + s * B16_STG_B) + wn;

#pragma unroll
            for (int ks = 0; ks < 2; ks++) {
                HFragA af[4];
                HFragB bf[4];
#pragma unroll
                for (int i = 0; i < 4; i++)
                    wmma::load_matrix_sync(af[i], Aw + (i * 16) * AH_LD + ks * 16, AH_LD);
#pragma unroll
                for (int j = 0; j < 4; j++)
                    wmma::load_matrix_sync(bf[j], Bw + (ks * 16) * B16_LD + j * 16, B16_LD);
#pragma unroll
                for (int i = 0; i < 4; i++)
#pragma unroll
                    for (int j = 0; j < 4; j++)
                        wmma::mma_sync(acc[i][j], af[i], bf[j], acc[i][j]);
            }
        }

        // epilogue: C[128 node][128 d] -> half2 atomicAdd into g_upd_h
        __syncthreads();
        float* Csm = (float*)smc;            // 128 x 132 floats
#pragma unroll
        for (int i = 0; i < 4; i++)
#pragma unroll
            for (int j = 0; j < 4; j++)
                wmma::store_matrix_sync(Csm + (wm + i * 16) * 132 + (wn + j * 16),
                                        acc[i][j], 132, wmma::mem_row_major);
        __syncthreads();

        const int c  = tid & 63;
        const int r0 = (tid >> 6) * 64;
#pragma unroll
        for (int i = 0; i < 64; i++) {
            const int row = r0 + i;
            if (node0 + row < cnt) {
                __half2 v = __floats2half2_rn(Csm[row * 132 + 2 * c],
                                              Csm[row * 132 + 2 * c + 1]);
                atomicAdd((__half2*)(g_upd_h + (size_t)nl[row] * KU
                                     + (r << 7) + 2 * c), v);
            }
        }
        __syncthreads();   // Csm reads done before next unit reuses smem
    }
}

// ---------------------------------------------------------------------------
// Kernel 3: stage2 gathered fp16 GEMM, BM=64 (2x the CTAs of R15 -> less
// latency-bound), folded self term. grid 256: tile = bx&127, split = bx>>7.
// ---------------------------------------------------------------------------
#define S2_BK   64
#define S2_LDA  72
#define S2_LDB  136
#define S2_AST  (64 * S2_LDA)           // 4608 halves
#define S2_BST  (S2_BK * S2_LDB)        // 8704 halves
#define S2_STG  (S2_AST + S2_BST)       // 13312 halves = 26624 B
#define SMEM_T  (3 * S2_STG * 2)        // 79872 B

__global__ __launch_bounds__(128) void stage2_kernel(
    const int* __restrict__ head_idx,
    const int* __restrict__ tail_idx,
    float*     __restrict__ out)       // [8192,128]
{
    extern __shared__ __half smh[];
    __shared__ int rowidx[64];

    const int tid    = threadIdx.x;
    const int wid    = tid >> 5;
    const int bx     = blockIdx.x;
    const int tile   = bx & 127;        // 128 tiles of 64 rows
    const int split  = bx >> 7;
    const int m0     = tile * 64;
    const int branch = tile >> 6;
    const int b0     = (tile & 63) * 64;

    const int* idxp = branch ? tail_idx : head_idx;
    if (tid < 64) rowidx[tid] = idxp[b0 + tid];
    __syncthreads();

    const uint32_t sm32 = (uint32_t)__cvta_generic_to_shared(smh);
    const int arow = tid >> 1;
    const int ah0  = (tid & 1) * 32;
    const size_t aoff_u = (size_t)rowidx[arow] * KU + ah0;
    const size_t aoff_e = (size_t)(m0 + arow) * DD + ah0;

    const int brow = tid >> 1;
    const int bh0  = (tid & 1) * 64;
    const int kstart = split * 576;

    auto issue = [&](int j) {
        const int s = j % 3;
        const int k0 = kstart + j * S2_BK;
        const uint32_t astage = sm32 + (uint32_t)(s * S2_STG * 2);
        const uint32_t bstage = astage + S2_AST * 2;
        const __half* asrc = (k0 < KU) ? (g_upd_h + aoff_u + k0)
                                       : (g_eh + aoff_e + (k0 - KU));
        const __half* bsrc = g_Bh + (size_t)(k0 + brow) * OUTD + bh0;
        const uint32_t a_dst = astage + (uint32_t)(arow * S2_LDA + ah0) * 2;
        const uint32_t b_dst = bstage + (uint32_t)(brow * S2_LDB + bh0) * 2;
#pragma unroll
        for (int c = 0; c < 4; c++)
            cp_async16(a_dst + c * 16, asrc + c * 8);
#pragma unroll
        for (int c = 0; c < 8; c++)
            cp_async16(b_dst + c * 16, bsrc + c * 8);
    };

    const int wm = (wid >> 1) * 32;     // 0 or 32
    const int wn = (wid & 1) * 64;      // 0 or 64

    HFragC acc[2][4];
#pragma unroll
    for (int i = 0; i < 2; i++)
#pragma unroll
        for (int j = 0; j < 4; j++) wmma::fill_fragment(acc[i][j], 0.0f);

    issue(0); cp_commit();
    issue(1); cp_commit();

    const int NIT = 576 / S2_BK;   // 9
    for (int it = 0; it < NIT; it++) {
        const int s = it % 3;
        asm volatile("cp.async.wait_group 1;\n" ::: "memory");
        __syncthreads();
        if (it + 2 < NIT) issue(it + 2);
        cp_commit();

        const __half* As = smh + s * S2_STG;
        const __half* Bs = As + S2_AST;
        const __half* Aw = As + wm * S2_LDA;
        const __half* Bw = Bs + wn;

#pragma unroll
        for (int ks = 0; ks < 4; ks++) {
            HFragA af[2];
            HFragB bf[4];
#pragma unroll
            for (int i = 0; i < 2; i++)
                wmma::load_matrix_sync(af[i], Aw + (i * 16) * S2_LDA + ks * 16, S2_LDA);
#pragma unroll
            for (int j = 0; j < 4; j++)
                wmma::load_matrix_sync(bf[j], Bw + (ks * 16) * S2_LDB + j * 16, S2_LDB);
#pragma unroll
            for (int i = 0; i < 2; i++)
#pragma unroll
                for (int j = 0; j < 4; j++)
                    wmma::mma_sync(acc[i][j], af[i], bf[j], acc[i][j]);
        }
    }

    __syncthreads();
    float* Csm = (float*)smh;            // 64 x 132 floats = 33792 B
#pragma unroll
    for (int i = 0; i < 2; i++)
#pragma unroll
        for (int j = 0; j < 4; j++)
            wmma::store_matrix_sync(Csm + (wm + i * 16) * 132 + (wn + j * 16),
                                    acc[i][j], 132, wmma::mem_row_major);
    __syncthreads();

#pragma unroll
    for (int i = 0; i < 64; i++)
        atomicAdd(&out[(size_t)(m0 + i) * OUTD + tid], Csm[i * 132 + tid]);
}

// ---------------------------------------------------------------------------
// Launch (4 launches per call)
// ---------------------------------------------------------------------------
extern "C" void kernel_launch(void* const* d_in, const int* in_sizes, int n_in,
                              void* d_out, int out_size) {
    const float* emb      = (const float*)d_in[0];
    const int*   head_idx = (const int*)  d_in[1];
    const float* head_e   = (const float*)d_in[2];
    const int*   tail_idx = (const int*)  d_in[3];
    const float* tail_e   = (const float*)d_in[4];
    const float* adj      = (const float*)d_in[5];
    const float* relK     = (const float*)d_in[6];
    const float* selfK    = (const float*)d_in[7];
    float* out = (float*)d_out;

    cudaFuncSetAttribute(stage1_kernel,
                         cudaFuncAttributeMaxDynamicSharedMemorySize, SMEM_S1);
    cudaFuncSetAttribute(stage2_kernel,
                         cudaFuncAttributeMaxDynamicSharedMemorySize, SMEM_T);

    // 1) zero output/upd/work + convert emb/e/relK/selfK
    prep_kernel<<<2048, 256>>>((float4*)out,
                               (const float2*)emb,
                               (const float2*)head_e,
                               (const float2*)tail_e,
                               (const float2*)relK,
                               (const float2*)selfK);
    // 2) compact distinct nodes
    compact_kernel<<<1, 1024>>>(head_idx, tail_idx);
    // 3) stage1: persistent dense per-node GEMM (atomic work queue)
    stage1_kernel<<<304, 128, SMEM_S1>>>(adj);
    // 4) stage2: gathered fp16 GEMM, BM=64 (+ self term) -> out
    stage2_kernel<<<256, 128, SMEM_T>>>(head_idx, tail_idx, out);
}

// round 17
// speedup vs baseline: 1.5001x; 1.5001x over previous
#include <cuda_runtime.h>
#include <cuda_fp16.h>
#include <cstdint>
#include <cstddef>
#include <mma.h>

using namespace nvcuda;

// ---------------------------------------------------------------------------
// Problem: N=4096, D=128, R=8, OUT=128, B=4096
// Node-dedup + K-split restructuring (R15 config, measured 210.7 us, plus
// stage2 deep-prefetch and atomic compaction):
//   compact: distinct nodes referenced by head_idx||tail_idx (~3542), any order
//   stage1 (dense, reg-fused cvt, K-split 4, static grid 1024):
//       upd_all[node][r*128+d] += sum_{n in split} adj[r,node,n]*emb[n,d]
//   stage2 (gather, BM=128, K-split 2, 4-stage pipeline):
//       out[m][o] = sum_k A2[m][k]*B2[k][o]
//       A2[m][k<1024] = upd_all[idx_m][k],  A2[m][1024+dd] = e_m[dd]
//       B2[k<1024][o] = relK_flat[k][o],    B2[1024+dd][o] = selfK[dd][o]
// Legacy wmma fp16 only (compute_103 PTX: no tcgen05).
// ---------------------------------------------------------------------------

#define NN    4096
#define DD    128
#define RR    8
#define OUTD  128
#define KU    (RR * DD)            // 1024
#define K2    (KU + DD)            // 1152

// Device-global scratch (no allocation):
__device__ __half g_emb_h[NN * DD];                // 1 MB
__device__ __half g_upd_h[(size_t)NN * KU];        // 8 MB  [node][r*128+d]
__device__ __half g_eh[(size_t)2 * NN * DD];       // 2 MB  [m][d] (head||tail)
__device__ __half g_Bh[K2 * OUTD];                 // 288 KB [k][o]
__device__ int    g_list[NN];                      // compacted node ids
__device__ int    g_cnt;                           // number of distinct nodes

__device__ __forceinline__ void cp_async16(uint32_t dst, const void* src) {
    asm volatile("cp.async.cg.shared.global [%0], [%1], 16;\n"
                 :: "r"(dst), "l"(src));
}
__device__ __forceinline__ void cp_commit() {
    asm volatile("cp.async.commit_group;\n" ::: "memory");
}

// ---------------------------------------------------------------------------
// Kernel 0: zero output + zero g_upd_h + convert emb/e/relK/selfK -> fp16
// grid 2048 x 256 = 524288 threads
// ---------------------------------------------------------------------------
__global__ void prep_kernel(float4* __restrict__ out,
                            const float2* __restrict__ emb2,
                            const float2* __restrict__ head_e2,
                            const float2* __restrict__ tail_e2,
                            const float2* __restrict__ relK2,
                            const float2* __restrict__ selfK2) {
    int i = blockIdx.x * blockDim.x + threadIdx.x;     // 0..524287
    if (i < 262144) out[i] = make_float4(0.f, 0.f, 0.f, 0.f);
    // zero g_upd_h: 8 MB = 524288 x 16 B
    {
        uint4 z = make_uint4(0u, 0u, 0u, 0u);
        ((uint4*)g_upd_h)[i] = z;
    }
    if (i < NN * DD / 2) {                             // emb
        float2 v = emb2[i];
        ((__half2*)g_emb_h)[i] = __floats2half2_rn(v.x, v.y);
    }
    if (i < 2 * NN * DD / 2) {                         // e (head||tail)
        float2 v = (i < NN * DD / 2) ? head_e2[i] : tail_e2[i - NN * DD / 2];
        ((__half2*)g_eh)[i] = __floats2half2_rn(v.x, v.y);
    }
    if (i < K2 * OUTD / 2) {                           // B2 (relK||selfK)
        float2 v = (i < KU * OUTD / 2) ? relK2[i] : selfK2[i - KU * OUTD / 2];
        ((__half2*)g_Bh)[i] = __floats2half2_rn(v.x, v.y);
    }
}

// ---------------------------------------------------------------------------
// Kernel 1: compact — distinct-node list via shared-memory marks + atomic
// counter (order irrelevant to stage1). Single block, 1024 threads.
// ---------------------------------------------------------------------------
__global__ __launch_bounds__(1024) void compact_kernel(
    const int* __restrict__ head_idx,
    const int* __restrict__ tail_idx) {
    __shared__ int sA[NN];
    __shared__ int scnt;
    const int tid = threadIdx.x;

#pragma unroll
    for (int k = 0; k < 4; k++) sA[tid + k * 1024] = 0;
    if (tid == 0) scnt = 0;
    __syncthreads();
#pragma unroll
    for (int k = 0; k < 8; k++) {
        int q = tid + k * 1024;                 // 0..8191
        int v = (q < 4096) ? head_idx[q] : tail_idx[q - 4096];
        sA[v] = 1;                              // benign races: all store 1
    }
    __syncthreads();
#pragma unroll
    for (int k = 0; k < 4; k++) {
        int i = tid + k * 1024;
        if (sA[i]) {
            int p = atomicAdd(&scnt, 1);        // warp-aggregated by ptxas
            g_list[p] = i;
        }
    }
    __syncthreads();
    const int cnt = scnt;
    if (tid == 0) g_cnt = cnt;
#pragma unroll
    for (int k = 0; k < 4; k++) {
        int i = tid + k * 1024;
        if (i >= cnt) g_list[i] = 0;            // pad tail with a valid node
    }
}

// ---------------------------------------------------------------------------
// wmma fragment types
// ---------------------------------------------------------------------------
typedef wmma::fragment<wmma::matrix_a, 16, 16, 16, __half, wmma::row_major> HFragA;
typedef wmma::fragment<wmma::matrix_b, 16, 16, 16, __half, wmma::row_major> HFragB;
typedef wmma::fragment<wmma::accumulator, 16, 16, 16, float> HFragC;

// ---------------------------------------------------------------------------
// Kernel 2: stage1 (EXACT R15 static-grid version, measured ~175 us).
//   grid.x = 1024: tile = bx&31, r = (bx>>5)&7, split = bx>>8.
//   Rows = compacted nodes [tile*128, +128) (tail padded, stores guarded).
//   Per CTA: K = 1024 (n in [split*1024, +1024)), 32 iters of BK=32.
//   Epilogue: fp16 half2 atomicAdd into g_upd_h (zeroed in prep).
// SMEM: Ah 2 x 128 x 40 halves [0,20480); B16 3 x 32 x 136 halves
// [20480,46592). Epilogue reuses smem as 128x132 fp32 (67584 B = alloc).
// ---------------------------------------------------------------------------
#define AH_LD     40
#define AH_STG_B  10240
#define B16_LD    136
#define B16_STG_B 8704
#define OFF_AH    0
#define OFF_B16   20480
#define SMEM_S1   (128 * 132 * 4)       // 67584
#define S1_NIT    32                    // 1024 / 32

__global__ __launch_bounds__(128, 2) void stage1_kernel(
    const float* __restrict__ adj)       // [8,4096,4096] fp32
{
    extern __shared__ char smc[];
    __shared__ int nl[128];

    const int tid   = threadIdx.x;
    const int wid   = tid >> 5;
    const int bx    = blockIdx.x;
    const int tile  = bx & 31;
    const int r     = (bx >> 5) & 7;
    const int split = bx >> 8;
    const int node0 = tile * 128;

    const int cnt = g_cnt;
    if (node0 >= cnt) return;            // uniform early exit; CLC backfills

    nl[tid] = g_list[node0 + tid];
    __syncthreads();

    const uint32_t sm32 = (uint32_t)__cvta_generic_to_shared(smc);
    const int nbase = split * 1024;
    const float* adjrow = adj + ((size_t)r << 24) + (size_t)nl[tid] * NN + nbase;

    // B loader: 32 rows x 128 halves; 4 threads/row, 32 halves (64 B) each
    const int brow = tid >> 2;
    const int bh0  = (tid & 3) * 32;

    auto issueB = [&](int j) {
        const int s = j % 3;
        const int n0 = nbase + j * 32;
        const uint32_t b_dst = sm32 + OFF_B16 + (uint32_t)s * B16_STG_B
                             + (uint32_t)(brow * B16_LD + bh0) * 2;
        const __half* bsrc = g_emb_h + (size_t)(n0 + brow) * DD + bh0;
#pragma unroll
        for (int c = 0; c < 4; c++)
            cp_async16(b_dst + c * 16, bsrc + c * 8);
    };

    const int wm = (wid >> 1) * 64;
    const int wn = (wid & 1) * 64;

    HFragC acc[4][4];
#pragma unroll
    for (int i = 0; i < 4; i++)
#pragma unroll
        for (int j = 0; j < 4; j++) wmma::fill_fragment(acc[i][j], 0.0f);

    // prologue: A regs for iter 0; B stages 0,1
    float4 abuf[8];
#pragma unroll
    for (int q = 0; q < 8; q++) abuf[q] = *(const float4*)(adjrow + q * 4);
    issueB(0); cp_commit();
    issueB(1); cp_commit();

    for (int it = 0; it < S1_NIT; it++) {
        const int s = it % 3;
        asm volatile("cp.async.wait_group 1;\n" ::: "memory");   // B(it) arrived

        // convert abuf -> Ah[it&1], 32 halves = 4 x STS.128
        {
            __half* dst = (__half*)(smc + OFF_AH + (it & 1) * AH_STG_B)
                        + tid * AH_LD;
#pragma unroll
            for (int q = 0; q < 4; q++) {
                float4 v0 = abuf[2 * q];
                float4 v1 = abuf[2 * q + 1];
                __half2 h0 = __floats2half2_rn(v0.x, v0.y);
                __half2 h1 = __floats2half2_rn(v0.z, v0.w);
                __half2 h2 = __floats2half2_rn(v1.x, v1.y);
                __half2 h3 = __floats2half2_rn(v1.z, v1.w);
                uint4 w;
                w.x = *(const uint32_t*)&h0;
                w.y = *(const uint32_t*)&h1;
                w.z = *(const uint32_t*)&h2;
                w.w = *(const uint32_t*)&h3;
                *(uint4*)(dst + q * 8) = w;
            }
        }
        // register prefetch A for iter it+1
        if (it + 1 < S1_NIT) {
            const float* src = adjrow + (it + 1) * 32;
#pragma unroll
            for (int q = 0; q < 8; q++) abuf[q] = *(const float4*)(src + q * 4);
        }

        __syncthreads();   // publishes Ah[it&1] + B stage s; closes wmma_{it-1}

        if (it + 2 < S1_NIT) issueB(it + 2);
        cp_commit();

        const __half* Aw = (const __half*)(smc + OFF_AH + (it & 1) * AH_STG_B)
                         + wm * AH_LD;
        const __half* Bw = (const __half*)(smc + OFF_B16 + s * B16_STG_B) + wn;

#pragma unroll
        for (int ks = 0; ks < 2; ks++) {
            HFragA af[4];
            HFragB bf[4];
#pragma unroll
            for (int i = 0; i < 4; i++)
                wmma::load_matrix_sync(af[i], Aw + (i * 16) * AH_LD + ks * 16, AH_LD);
#pragma unroll
            for (int j = 0; j < 4; j++)
                wmma::load_matrix_sync(bf[j], Bw + (ks * 16) * B16_LD + j * 16, B16_LD);
#pragma unroll
            for (int i = 0; i < 4; i++)
#pragma unroll
                for (int j = 0; j < 4; j++)
                    wmma::mma_sync(acc[i][j], af[i], bf[j], acc[i][j]);
        }
    }

    // epilogue: C[128 node][128 d] -> half2 atomicAdd into g_upd_h
    __syncthreads();
    float* Csm = (float*)smc;            // 128 x 132 floats = 67584 B
#pragma unroll
    for (int i = 0; i < 4; i++)
#pragma unroll
        for (int j = 0; j < 4; j++)
            wmma::store_matrix_sync(Csm + (wm + i * 16) * 132 + (wn + j * 16),
                                    acc[i][j], 132, wmma::mem_row_major);
    __syncthreads();

    const int c  = tid & 63;             // half2 column
    const int r0 = (tid >> 6) * 64;      // row half
#pragma unroll
    for (int i = 0; i < 64; i++) {
        const int row = r0 + i;
        if (node0 + row < cnt) {
            __half2 v = __floats2half2_rn(Csm[row * 132 + 2 * c],
                                          Csm[row * 132 + 2 * c + 1]);
            atomicAdd((__half2*)(g_upd_h + (size_t)nl[row] * KU + (r << 7) + 2 * c), v);
        }
    }
}

// ---------------------------------------------------------------------------
// Kernel 3: stage2 gathered fp16 GEMM, BM=128, K-split 2 (the measured-22us
// R15 shape), upgraded to a 4-stage pipeline with prefetch depth 3.
//   grid 128: tile = bx&63 (m0=tile*128), split = bx>>6 (K 576/576).
// ---------------------------------------------------------------------------
#define BKH     64
#define LDAH    72
#define LDBH    136
#define ASTGH   (128 * LDAH)            // 9216 halves
#define BSTGH   (BKH * LDBH)            // 8704 halves
#define STGH    (ASTGH + BSTGH)         // 17920 halves = 35840 B
#define S2_NS   4
#define SMEM_T  (S2_NS * STGH * 2)      // 143360 B

__global__ __launch_bounds__(128) void stage2_kernel(
    const int* __restrict__ head_idx,
    const int* __restrict__ tail_idx,
    float*     __restrict__ out)       // [8192,128]
{
    extern __shared__ __half smh[];
    __shared__ int rowidx[128];

    const int tid   = threadIdx.x;
    const int wid   = tid >> 5;
    const int bx    = blockIdx.x;
    const int tile  = bx & 63;
    const int split = bx >> 6;
    const int m0    = tile * 128;
    const int branch = tile >> 5;
    const int b0    = (tile & 31) * 128;

    const int* idxp = branch ? tail_idx : head_idx;
    rowidx[tid] = idxp[b0 + tid];
    __syncthreads();

    const uint32_t sm32 = (uint32_t)__cvta_generic_to_shared(smh);
    const size_t aoff_u = (size_t)rowidx[tid] * KU;
    const size_t aoff_e = (size_t)(m0 + tid) * DD;

    const int brow = tid >> 1;
    const int bh0  = (tid & 1) * 64;
    const int kstart = split * 576;

    auto issue = [&](int j) {
        const int s = j % S2_NS;
        const int k0 = kstart + j * BKH;
        const uint32_t astage = sm32 + (uint32_t)(s * STGH * 2);
        const uint32_t bstage = astage + ASTGH * 2;
        const __half* asrc = (k0 < KU) ? (g_upd_h + aoff_u + k0)
                                       : (g_eh + aoff_e + (k0 - KU));
        const __half* bsrc = g_Bh + (size_t)(k0 + brow) * OUTD + bh0;
        const uint32_t a_dst = astage + (uint32_t)tid * (LDAH * 2);
        const uint32_t b_dst = bstage + (uint32_t)(brow * LDBH + bh0) * 2;
#pragma unroll
        for (int c = 0; c < 8; c++) {
            cp_async16(a_dst + c * 16, asrc + c * 8);
            cp_async16(b_dst + c * 16, bsrc + c * 8);
        }
    };

    const int wm = (wid >> 1) * 64;
    const int wn = (wid & 1) * 64;

    HFragC acc[4][4];
#pragma unroll
    for (int i = 0; i < 4; i++)
#pragma unroll
        for (int j = 0; j < 4; j++) wmma::fill_fragment(acc[i][j], 0.0f);

    // prologue: 3 stages in flight
    issue(0); cp_commit();
    issue(1); cp_commit();
    issue(2); cp_commit();

    const int NIT = 576 / BKH;   // 9
    for (int it = 0; it < NIT; it++) {
        const int s = it % S2_NS;
        asm volatile("cp.async.wait_group 2;\n" ::: "memory");   // group it done
        __syncthreads();          // all warps past wmma_{it-1}; stage (it-1)%4 free
        if (it + 3 < NIT) issue(it + 3);
        cp_commit();

        const __half* As = smh + s * STGH;
        const __half* Bs = As + ASTGH;
        const __half* Aw = As + wm * LDAH;
        const __half* Bw = Bs + wn;

#pragma unroll
        for (int ks = 0; ks < 4; ks++) {
            HFragA af[4];
            HFragB bf[4];
#pragma unroll
            for (int i = 0; i < 4; i++)
                wmma::load_matrix_sync(af[i], Aw + (i * 16) * LDAH + ks * 16, LDAH);
#pragma unroll
            for (int j = 0; j < 4; j++)
                wmma::load_matrix_sync(bf[j], Bw + (ks * 16) * LDBH + j * 16, LDBH);
#pragma unroll
            for (int i = 0; i < 4; i++)
#pragma unroll
                for (int j = 0; j < 4; j++)
                    wmma::mma_sync(acc[i][j], af[i], bf[j], acc[i][j]);
        }
    }

    // epilogue: stage C fp32 in smem, coalesced atomicAdd (out zeroed in prep)
    __syncthreads();
    float* Csm = (float*)smh;
#pragma unroll
    for (int i = 0; i < 4; i++)
#pragma unroll
        for (int j = 0; j < 4; j++)
            wmma::store_matrix_sync(Csm + (wm + i * 16) * 132 + (wn + j * 16),
                                    acc[i][j], 132, wmma::mem_row_major);
    __syncthreads();

#pragma unroll
    for (int i = 0; i < 128; i++)
        atomicAdd(&out[(size_t)(m0 + i) * OUTD + tid], Csm[i * 132 + tid]);
}

// ---------------------------------------------------------------------------
// Launch (4 launches per call)
// ---------------------------------------------------------------------------
extern "C" void kernel_launch(void* const* d_in, const int* in_sizes, int n_in,
                              void* d_out, int out_size) {
    const float* emb      = (const float*)d_in[0];
    const int*   head_idx = (const int*)  d_in[1];
    const float* head_e   = (const float*)d_in[2];
    const int*   tail_idx = (const int*)  d_in[3];
    const float* tail_e   = (const float*)d_in[4];
    const float* adj      = (const float*)d_in[5];
    const float* relK     = (const float*)d_in[6];
    const float* selfK    = (const float*)d_in[7];
    float* out = (float*)d_out;

    cudaFuncSetAttribute(stage1_kernel,
                         cudaFuncAttributeMaxDynamicSharedMemorySize, SMEM_S1);
    cudaFuncSetAttribute(stage2_kernel,
                         cudaFuncAttributeMaxDynamicSharedMemorySize, SMEM_T);

    // 1) zero output + zero g_upd_h + convert emb/e/relK/selfK
    prep_kernel<<<2048, 256>>>((float4*)out,
                               (const float2*)emb,
                               (const float2*)head_e,
                               (const float2*)tail_e,
                               (const float2*)relK,
                               (const float2*)selfK);
    // 2) compact distinct nodes (atomic, unordered)
    compact_kernel<<<1, 1024>>>(head_idx, tail_idx);
    // 3) stage1: dense per-node GEMM, reg-fused cvt, K-split 4, static grid
    stage1_kernel<<<1024, 128, SMEM_S1>>>(adj);
    // 4) stage2: gathered fp16 GEMM, BM=128, 4-stage pipeline (+ self term)
    stage2_kernel<<<128, 128, SMEM_T>>>(head_idx, tail_idx, out);
}